// round 12
// baseline (speedup 1.0000x reference)
#include <cuda_runtime.h>
#include <cuda_fp16.h>
#include <cstdint>

#define D 256
#define LNUM 3
#define RNUM 4
#define NRXN 10
#define NMAX 100000
#define EMAX 400000
#define GMAX 2000
#define KDIM 1280    // halves: [x(256) | S0..S3 (4*256)]
#define ENCD 768
#define GCTX 778
#define NCTX 1802

// ---------------- scratch ----------------
__device__ __half d_XA[(size_t)NMAX * KDIM];
__device__ __half d_XB[(size_t)NMAX * KDIM];
__device__ __half d_Wbig[LNUM * D * KDIM];   // [l][n][k], fp16
__device__ int    d_DegI[NMAX];
__device__ float  d_InvDeg[NMAX];
__device__ int    d_Off[NMAX];
__device__ int    d_Cursor[NMAX];
__device__ int    d_CsrE[EMAX];              // packed src*4 + type, grouped by dst

// ---------------- helpers ----------------
__device__ __forceinline__ uint32_t smem_u32(const void* p) {
    uint32_t a;
    asm("{ .reg .u64 t; cvta.to.shared.u64 t, %1; cvt.u32.u64 %0, t; }" : "=r"(a) : "l"(p));
    return a;
}
__device__ __forceinline__ void mma16(float* c, const uint32_t* a, uint32_t b0, uint32_t b1) {
    asm volatile("mma.sync.aligned.m16n8k16.row.col.f32.f16.f16.f32 "
        "{%0,%1,%2,%3}, {%4,%5,%6,%7}, {%8,%9}, {%0,%1,%2,%3};"
        : "+f"(c[0]), "+f"(c[1]), "+f"(c[2]), "+f"(c[3])
        : "r"(a[0]), "r"(a[1]), "r"(a[2]), "r"(a[3]), "r"(b0), "r"(b1));
}
__device__ __forceinline__ void ldmx4(uint32_t* r, uint32_t addr) {
    asm volatile("ldmatrix.sync.aligned.m8n8.x4.shared.b16 {%0,%1,%2,%3}, [%4];"
        : "=r"(r[0]), "=r"(r[1]), "=r"(r[2]), "=r"(r[3]) : "r"(addr));
}

// ---------------- fused setup: wcat + init + zero DegI (independent jobs) ----------------
__global__ void k_setup(const float* __restrict__ nf, const float* __restrict__ flagW,
                        const float* __restrict__ flagb, const int* __restrict__ mask,
                        const float* __restrict__ Wself, const float* __restrict__ Wrel,
                        __half* __restrict__ X, float* __restrict__ out_node,
                        int n, int wcatB, int initB) {
    const int b   = blockIdx.x;
    const int tid = threadIdx.x;
    if (b < wcatB) {
        // ---- wcat: Wbig[l][nn][k] fp16 ----
        int i = b * 256 + tid;
        if (i >= LNUM * D * KDIM) return;
        int l   = i / (D * KDIM);
        int rem = i % (D * KDIM);
        int nn = rem / KDIM, k = rem % KDIM;
        float v;
        if (k < D) {
            v = Wself[(size_t)l * D * D + (size_t)k * D + nn];
        } else {
            int r  = (k - D) >> 8;
            int kk = (k - D) & 255;
            v = Wrel[(((size_t)l * RNUM + r) * D + kk) * (size_t)D + nn];
        }
        d_Wbig[i] = __float2half_rn(v);
    } else if (b < wcatB + initB) {
        // ---- init: x0 fp16 -> X cols 0..255; nf copy -> out [768:1024) ----
        long long i = (long long)(b - wcatB) * 256 + tid;
        if (i >= (long long)n * 64) return;
        int node = (int)(i >> 6);
        int c4   = (int)(i & 63);
        float4 v  = reinterpret_cast<const float4*>(nf)[i];
        float4 bb = reinterpret_cast<const float4*>(flagb)[c4];
        float  m  = (mask[node] != 0) ? 1.0f : 0.0f;
        float4 w  = reinterpret_cast<const float4*>(flagW + D)[c4];
        __half2 h0 = __floats2half2_rn(v.x + bb.x + m * w.x, v.y + bb.y + m * w.y);
        __half2 h1 = __floats2half2_rn(v.z + bb.z + m * w.z, v.w + bb.w + m * w.w);
        uint2 st;
        st.x = *reinterpret_cast<uint32_t*>(&h0);
        st.y = *reinterpret_cast<uint32_t*>(&h1);
        *reinterpret_cast<uint2*>(X + (size_t)node * KDIM + (c4 << 2)) = st;
        float* op = out_node + (size_t)node * NCTX + ENCD + (c4 << 2);
        reinterpret_cast<float2*>(op)[0] = make_float2(v.x, v.y);
        reinterpret_cast<float2*>(op)[1] = make_float2(v.z, v.w);
    } else {
        // ---- zero DegI ----
        int i = (b - wcatB - initB) * 256 + tid;
        if (i < n) d_DegI[i] = 0;
    }
}

__global__ void k_deg(const int* __restrict__ dst, int e) {
    int i = blockIdx.x * blockDim.x + threadIdx.x;
    if (i < e) atomicAdd(&d_DegI[dst[i]], 1);
}

// single-block chunked exclusive scan of DegI -> Off, Cursor, InvDeg
__global__ void __launch_bounds__(1024) k_scan(int n) {
    __shared__ int ps[1024];
    const int t = threadIdx.x;
    const int chunk = (n + 1023) >> 10;
    const int s  = t * chunk;
    const int e2 = min(s + chunk, n);
    int sum = 0;
    for (int i = s; i < e2; i++) sum += d_DegI[i];
    ps[t] = sum;
    __syncthreads();
    for (int off = 1; off < 1024; off <<= 1) {
        int v = (t >= off) ? ps[t - off] : 0;
        __syncthreads();
        if (t >= off) ps[t] += v;
        __syncthreads();
    }
    int base = (t == 0) ? 0 : ps[t - 1];
    for (int i = s; i < e2; i++) {
        int dg = d_DegI[i];
        d_Off[i] = base;
        d_Cursor[i] = base;
        d_InvDeg[i] = 1.0f / fmaxf((float)dg, 1.0f);
        base += dg;
    }
}

__global__ void k_scatter(const int* __restrict__ src, const int* __restrict__ dst,
                          const int* __restrict__ typ, int e) {
    int i = blockIdx.x * blockDim.x + threadIdx.x;
    if (i >= e) return;
    int pos = atomicAdd(&d_Cursor[dst[i]], 1);
    d_CsrE[pos] = (src[i] << 2) | typ[i];
}

// ---------------- CSR aggregation: warp per dst node, 4-edge MLP chunks ----------------
__global__ void __launch_bounds__(256) k_agg(const __half* __restrict__ Xr,
                                             __half* __restrict__ X, int n, int e) {
    int w    = (blockIdx.x * blockDim.x + threadIdx.x) >> 5;
    int lane = threadIdx.x & 31;
    if (w >= n) return;
    const int beg = d_Off[w];
    const int end = (w == n - 1) ? e : d_Off[w + 1];

    float acc[4][8];
#pragma unroll
    for (int t = 0; t < 4; t++)
#pragma unroll
        for (int q = 0; q < 8; q++) acc[t][q] = 0.0f;

    auto accum = [&](uint4 v, int t) {
        const __half2* hp = reinterpret_cast<const __half2*>(&v);
        float2 f0 = __half22float2(hp[0]);
        float2 f1 = __half22float2(hp[1]);
        float2 f2 = __half22float2(hp[2]);
        float2 f3 = __half22float2(hp[3]);
        float* a = acc[t];
        a[0] += f0.x; a[1] += f0.y; a[2] += f1.x; a[3] += f1.y;
        a[4] += f2.x; a[5] += f2.y; a[6] += f3.x; a[7] += f3.y;
    };

    int j = beg;
    for (; j + 4 <= end; j += 4) {
        // 4 independent index loads, then 4 independent row gathers (MLP=4)
        int p0 = d_CsrE[j + 0];
        int p1 = d_CsrE[j + 1];
        int p2 = d_CsrE[j + 2];
        int p3 = d_CsrE[j + 3];
        uint4 v0 = reinterpret_cast<const uint4*>(Xr + (size_t)(p0 >> 2) * KDIM)[lane];
        uint4 v1 = reinterpret_cast<const uint4*>(Xr + (size_t)(p1 >> 2) * KDIM)[lane];
        uint4 v2 = reinterpret_cast<const uint4*>(Xr + (size_t)(p2 >> 2) * KDIM)[lane];
        uint4 v3 = reinterpret_cast<const uint4*>(Xr + (size_t)(p3 >> 2) * KDIM)[lane];
        accum(v0, p0 & 3);
        accum(v1, p1 & 3);
        accum(v2, p2 & 3);
        accum(v3, p3 & 3);
    }
    for (; j < end; j++) {
        int pk = d_CsrE[j];
        uint4 v = reinterpret_cast<const uint4*>(Xr + (size_t)(pk >> 2) * KDIM)[lane];
        accum(v, pk & 3);
    }

    const float id = d_InvDeg[w];
#pragma unroll
    for (int t = 0; t < 4; t++) {
        __half2 h0 = __floats2half2_rn(acc[t][0] * id, acc[t][1] * id);
        __half2 h1 = __floats2half2_rn(acc[t][2] * id, acc[t][3] * id);
        __half2 h2 = __floats2half2_rn(acc[t][4] * id, acc[t][5] * id);
        __half2 h3 = __floats2half2_rn(acc[t][6] * id, acc[t][7] * id);
        uint4 st;
        st.x = *reinterpret_cast<uint32_t*>(&h0);
        st.y = *reinterpret_cast<uint32_t*>(&h1);
        st.z = *reinterpret_cast<uint32_t*>(&h2);
        st.w = *reinterpret_cast<uint32_t*>(&h3);
        reinterpret_cast<uint4*>(X + (size_t)w * KDIM + D + (t << 8))[lane] = st;
    }
}

// ---------------- fused fp16 mma.sync GEMM (4-stage cp.async, prefetch distance 3) ------------
#define BM 128
#define BN 256
#define KT 32                  // halves per k-tile
#define NKT (KDIM / KT)        // 40
#define ASTRB 80               // padded row stride bytes (32 halves + 8 pad)
#define ABYTES (BM * ASTRB)    // 10240
#define BBYTES (BN * ASTRB)    // 20480
#define STGB (ABYTES + BBYTES) // 30720
#define NSTAGE 4
#define GEMM_SMEM (NSTAGE * STGB)   // 122880

__global__ void __launch_bounds__(256, 1)
k_gemm(const __half* __restrict__ A, const __half* __restrict__ Wb,
       const float* __restrict__ bias, float* __restrict__ out_node,
       __half* __restrict__ xnext, int l, int M)
{
    extern __shared__ char smem[];
    const int tid    = threadIdx.x;
    const int lane   = tid & 31;
    const int wid    = tid >> 5;
    const int warp_m = wid & 1;
    const int warp_n = wid >> 1;
    const int brow   = blockIdx.x * BM;
    const uint32_t sbase = smem_u32(smem);

    float acc[4][8][4];
#pragma unroll
    for (int a = 0; a < 4; a++)
#pragma unroll
        for (int b = 0; b < 8; b++)
#pragma unroll
            for (int c = 0; c < 4; c++) acc[a][b][c] = 0.0f;

    // preload epilogue bias (16 values per thread, reused 8x)
    float2 breg_bias[8];
#pragma unroll
    for (int n8 = 0; n8 < 8; n8++) {
        int c = warp_n * 64 + (n8 << 3) + ((lane & 3) << 1);
        breg_bias[n8] = *reinterpret_cast<const float2*>(bias + c);
    }

    auto issue = [&](int kt) {
        const int buf = kt & (NSTAGE - 1);
        const uint32_t abase = sbase + buf * STGB;
        const uint32_t bbase = abase + ABYTES;
        const int k0 = kt * KT;
#pragma unroll
        for (int i = 0; i < 2; i++) {           // A: 512 16B-chunks
            int j = tid + (i << 8);
            int row = j >> 2, c = j & 3;
            int gr = brow + row;
            const __half* sp = A + (size_t)(gr < M ? gr : 0) * KDIM + k0 + (c << 3);
            uint32_t dp = abase + row * ASTRB + (c << 4);
            uint32_t sz = (gr < M) ? 16u : 0u;
            asm volatile("cp.async.cg.shared.global [%0], [%1], 16, %2;"
                         :: "r"(dp), "l"(sp), "r"(sz));
        }
#pragma unroll
        for (int i = 0; i < 4; i++) {           // B: 1024 16B-chunks
            int j = tid + (i << 8);
            int row = j >> 2, c = j & 3;
            const __half* sp = Wb + (size_t)row * KDIM + k0 + (c << 3);
            uint32_t dp = bbase + row * ASTRB + (c << 4);
            asm volatile("cp.async.cg.shared.global [%0], [%1], 16;"
                         :: "r"(dp), "l"(sp));
        }
        asm volatile("cp.async.commit_group;");
    };

    issue(0);
    issue(1);
    issue(2);

#pragma unroll 1
    for (int kt = 0; kt < NKT; kt++) {
        if (kt < NKT - 2)       asm volatile("cp.async.wait_group 2;");
        else if (kt == NKT - 2) asm volatile("cp.async.wait_group 1;");
        else                    asm volatile("cp.async.wait_group 0;");
        __syncthreads();
        if (kt + 3 < NKT) issue(kt + 3);

        const int buf = kt & (NSTAGE - 1);
        const uint32_t abase = sbase + buf * STGB + (warp_m * 64) * ASTRB;
        const uint32_t bbase = sbase + buf * STGB + ABYTES + (warp_n * 64) * ASTRB;

        uint32_t breg[8][4];
#pragma unroll
        for (int n8 = 0; n8 < 8; n8++) {
            uint32_t addr = bbase + ((n8 << 3) + (lane & 7)) * ASTRB + ((lane >> 3) << 4);
            ldmx4(breg[n8], addr);
        }
#pragma unroll
        for (int kh = 0; kh < 2; kh++) {
            uint32_t areg[4][4];
#pragma unroll
            for (int mt = 0; mt < 4; mt++) {
                uint32_t addr = abase + ((mt << 4) + (lane & 15)) * ASTRB
                              + (kh << 5) + ((lane >> 4) << 4);
                ldmx4(areg[mt], addr);
            }
#pragma unroll
            for (int mt = 0; mt < 4; mt++)
#pragma unroll
                for (int n8 = 0; n8 < 8; n8++)
                    mma16(acc[mt][n8], areg[mt], breg[n8][(kh << 1)], breg[n8][(kh << 1) + 1]);
        }
    }

    // ---- epilogue: bias + relu -> out fp32; xnext fp16 ----
#pragma unroll
    for (int mt = 0; mt < 4; mt++) {
        int r0 = brow + warp_m * 64 + (mt << 4) + (lane >> 2);
#pragma unroll
        for (int hf = 0; hf < 2; hf++) {
            int r = r0 + (hf << 3);
            if (r < M) {
#pragma unroll
                for (int n8 = 0; n8 < 8; n8++) {
                    int c = warp_n * 64 + (n8 << 3) + ((lane & 3) << 1);
                    float v0 = fmaxf(acc[mt][n8][(hf << 1) + 0] + breg_bias[n8].x, 0.0f);
                    float v1 = fmaxf(acc[mt][n8][(hf << 1) + 1] + breg_bias[n8].y, 0.0f);
                    *reinterpret_cast<float2*>(out_node + (size_t)r * NCTX + l * D + c) =
                        make_float2(v0, v1);
                    if (xnext) {
                        __half2 hv = __floats2half2_rn(v0, v1);
                        *reinterpret_cast<uint32_t*>(xnext + (size_t)r * KDIM + c) =
                            *reinterpret_cast<uint32_t*>(&hv);
                    }
                }
            }
        }
    }
}

// ---------------- fused pooling + broadcast: one block per graph (batch sorted) --------------
__global__ void __launch_bounds__(256)
k_pool(const int* __restrict__ batch, const int* __restrict__ reaction,
       float* __restrict__ out_node, float* __restrict__ gout, int n) {
    __shared__ float gctx[GCTX];
    const int gg  = blockIdx.x;
    const int tid = threadIdx.x;
    int lo = 0, hi = n;
    while (lo < hi) { int m = (lo + hi) >> 1; if (batch[m] < gg) lo = m + 1; else hi = m; }
    const int s = lo;
    hi = n;
    while (lo < hi) { int m = (lo + hi) >> 1; if (batch[m] <= gg) lo = m + 1; else hi = m; }
    const int e2 = lo;
    const float inv = 1.0f / fmaxf((float)(e2 - s), 1.0f);
    float a0 = 0.f, a1 = 0.f, a2 = 0.f;
    for (int node = s; node < e2; node++) {
        const float* row = out_node + (size_t)node * NCTX;
        a0 += row[tid];
        a1 += row[tid + 256];
        a2 += row[tid + 512];
    }
    gctx[tid]       = a0 * inv;
    gctx[tid + 256] = a1 * inv;
    gctx[tid + 512] = a2 * inv;
    if (tid < NRXN) gctx[ENCD + tid] = (tid == reaction[gg]) ? 1.0f : 0.0f;
    __syncthreads();
    float* gp = gout + (size_t)gg * GCTX;
    for (int c = tid; c < GCTX; c += 256) gp[c] = gctx[c];
    for (int node = s; node < e2; node++) {
        float* op = out_node + (size_t)node * NCTX + ENCD + D;
        for (int c = tid; c < GCTX; c += 256) op[c] = gctx[c];
    }
}

// ---------------- host launcher ----------------
extern "C" void kernel_launch(void* const* d_in, const int* in_sizes, int n_in,
                              void* d_out, int out_size) {
    const float* node_feature = (const float*)d_in[0];
    const float* flag_W       = (const float*)d_in[1];
    const float* flag_b       = (const float*)d_in[2];
    const float* W_self       = (const float*)d_in[3];
    const float* b_self       = (const float*)d_in[4];
    const float* W_rel        = (const float*)d_in[5];
    const int*   edge_src     = (const int*)d_in[6];
    const int*   edge_dst     = (const int*)d_in[7];
    const int*   edge_type    = (const int*)d_in[8];
    const int*   batch        = (const int*)d_in[9];
    const int*   reaction     = (const int*)d_in[10];
    const int*   center_mask  = (const int*)d_in[11];

    const int n = in_sizes[9];
    const int e = in_sizes[6];
    const int g = in_sizes[10];

    float* out  = (float*)d_out;
    float* gout = out + (size_t)n * NCTX;

    const int TPB = 256;
    auto blocks = [](long long total, int tpb) { return (unsigned)((total + tpb - 1) / tpb); };

    cudaFuncSetAttribute(k_gemm, cudaFuncAttributeMaxDynamicSharedMemorySize, GEMM_SMEM);

    __half *xa, *xb, *wb;
    cudaGetSymbolAddress((void**)&xa, d_XA);
    cudaGetSymbolAddress((void**)&xb, d_XB);
    cudaGetSymbolAddress((void**)&wb, d_Wbig);

    // ---- fused setup (wcat + init + zero DegI), then CSR build ----
    const int wcatB = (LNUM * D * KDIM + 255) / 256;
    const int initB = (int)(((long long)n * 64 + 255) / 256);
    const int zeroB = (n + 255) / 256;
    k_setup<<<wcatB + initB + zeroB, TPB>>>(node_feature, flag_W, flag_b, center_mask,
                                            W_self, W_rel, xa, out, n, wcatB, initB);
    k_deg<<<blocks(e, TPB), TPB>>>(edge_dst, e);
    k_scan<<<1, 1024>>>(n);
    k_scatter<<<blocks(e, TPB), TPB>>>(edge_src, edge_dst, edge_type, e);

    __half* cur = xa;
    __half* nxt = xb;
    const unsigned gemm_grid = blocks(n, BM);
    for (int l = 0; l < LNUM; l++) {
        k_agg<<<blocks((long long)n * 32, TPB), TPB>>>(cur, cur, n, e);
        k_gemm<<<gemm_grid, 256, GEMM_SMEM>>>(cur, wb + (size_t)l * D * KDIM,
                                              b_self + (size_t)l * D, out,
                                              (l < LNUM - 1) ? nxt : nullptr, l, n);
        if (l < LNUM - 1) { __half* t = cur; cur = nxt; nxt = t; }
    }

    k_pool<<<g, 256>>>(batch, reaction, out, gout, n);
}

// round 13
// speedup vs baseline: 1.1346x; 1.1346x over previous
#include <cuda_runtime.h>
#include <cuda_fp16.h>
#include <cstdint>

#define D 256
#define LNUM 3
#define RNUM 4
#define NRXN 10
#define NMAX 100000
#define EMAX 400000
#define GMAX 2000
#define KDIM 1280    // halves: [x(256) | S0..S3 (4*256)]
#define ENCD 768
#define GCTX 778
#define NCTX 1802

// ---------------- scratch ----------------
__device__ __half d_XA[(size_t)NMAX * KDIM];
__device__ __half d_XB[(size_t)NMAX * KDIM];
__device__ __half d_Wbig[LNUM * D * KDIM];   // [l][n][k], fp16
__device__ int    d_DegI[NMAX];
__device__ float  d_InvDeg[NMAX];
__device__ int    d_Off[NMAX];
__device__ int    d_Cursor[NMAX];
__device__ int    d_CsrE[EMAX];              // packed src*4 + type, grouped by dst

// ---------------- helpers ----------------
__device__ __forceinline__ uint32_t smem_u32(const void* p) {
    uint32_t a;
    asm("{ .reg .u64 t; cvta.to.shared.u64 t, %1; cvt.u32.u64 %0, t; }" : "=r"(a) : "l"(p));
    return a;
}
__device__ __forceinline__ void mma16(float* c, const uint32_t* a, uint32_t b0, uint32_t b1) {
    asm volatile("mma.sync.aligned.m16n8k16.row.col.f32.f16.f16.f32 "
        "{%0,%1,%2,%3}, {%4,%5,%6,%7}, {%8,%9}, {%0,%1,%2,%3};"
        : "+f"(c[0]), "+f"(c[1]), "+f"(c[2]), "+f"(c[3])
        : "r"(a[0]), "r"(a[1]), "r"(a[2]), "r"(a[3]), "r"(b0), "r"(b1));
}
__device__ __forceinline__ void ldmx4(uint32_t* r, uint32_t addr) {
    asm volatile("ldmatrix.sync.aligned.m8n8.x4.shared.b16 {%0,%1,%2,%3}, [%4];"
        : "=r"(r[0]), "=r"(r[1]), "=r"(r[2]), "=r"(r[3]) : "r"(addr));
}

// ---------------- small kernels ----------------
__global__ void k_zero_i(int* p, int n) {
    int i = blockIdx.x * blockDim.x + threadIdx.x;
    if (i < n) p[i] = 0;
}

// x0 = nf + flag_b + mask*flag_W[1] (fp16 RNE -> X cols 0..255); nf copy -> out [768:1024)
__global__ void k_init(const float* __restrict__ nf, const float* __restrict__ flagW,
                       const float* __restrict__ flagb, const int* __restrict__ mask,
                       __half* __restrict__ X, float* __restrict__ out_node, int n) {
    long long i = (long long)blockIdx.x * blockDim.x + threadIdx.x;
    if (i >= (long long)n * 64) return;
    int node = (int)(i >> 6);
    int c4   = (int)(i & 63);
    float4 v = reinterpret_cast<const float4*>(nf)[i];
    float4 b = reinterpret_cast<const float4*>(flagb)[c4];
    float  m = (mask[node] != 0) ? 1.0f : 0.0f;
    float4 w = reinterpret_cast<const float4*>(flagW + D)[c4];
    __half2 h0 = __floats2half2_rn(v.x + b.x + m * w.x, v.y + b.y + m * w.y);
    __half2 h1 = __floats2half2_rn(v.z + b.z + m * w.z, v.w + b.w + m * w.w);
    uint2 st;
    st.x = *reinterpret_cast<uint32_t*>(&h0);
    st.y = *reinterpret_cast<uint32_t*>(&h1);
    *reinterpret_cast<uint2*>(X + (size_t)node * KDIM + (c4 << 2)) = st;
    float* op = out_node + (size_t)node * NCTX + ENCD + (c4 << 2);
    reinterpret_cast<float2*>(op)[0] = make_float2(v.x, v.y);
    reinterpret_cast<float2*>(op)[1] = make_float2(v.z, v.w);
}

__global__ void k_deg(const int* __restrict__ dst, int e) {
    int i = blockIdx.x * blockDim.x + threadIdx.x;
    if (i < e) atomicAdd(&d_DegI[dst[i]], 1);
}
__global__ void k_invdeg(int n) {
    int i = blockIdx.x * blockDim.x + threadIdx.x;
    if (i < n) d_InvDeg[i] = 1.0f / fmaxf((float)d_DegI[i], 1.0f);
}

// single-block chunked exclusive scan of DegI -> Off, Cursor
__global__ void __launch_bounds__(1024) k_scan(int n) {
    __shared__ int ps[1024];
    const int t = threadIdx.x;
    const int chunk = (n + 1023) >> 10;
    const int s  = t * chunk;
    const int e2 = min(s + chunk, n);
    int sum = 0;
    for (int i = s; i < e2; i++) sum += d_DegI[i];
    ps[t] = sum;
    __syncthreads();
    for (int off = 1; off < 1024; off <<= 1) {
        int v = (t >= off) ? ps[t - off] : 0;
        __syncthreads();
        if (t >= off) ps[t] += v;
        __syncthreads();
    }
    int base = (t == 0) ? 0 : ps[t - 1];
    for (int i = s; i < e2; i++) {
        d_Off[i] = base;
        d_Cursor[i] = base;
        base += d_DegI[i];
    }
}

__global__ void k_scatter(const int* __restrict__ src, const int* __restrict__ dst,
                          const int* __restrict__ typ, int e) {
    int i = blockIdx.x * blockDim.x + threadIdx.x;
    if (i >= e) return;
    int pos = atomicAdd(&d_Cursor[dst[i]], 1);
    d_CsrE[pos] = (src[i] << 2) | typ[i];
}

// Wbig[l][n][k] fp16: k<256 -> W_self[l][k][n]; else r=(k-256)>>8, kk=(k-256)&255 -> W_rel[l][r][kk][n]
__global__ void k_wcat(const float* __restrict__ Wself, const float* __restrict__ Wrel) {
    int i = blockIdx.x * blockDim.x + threadIdx.x;
    if (i >= LNUM * D * KDIM) return;
    int l   = i / (D * KDIM);
    int rem = i % (D * KDIM);
    int n = rem / KDIM, k = rem % KDIM;
    float v;
    if (k < D) {
        v = Wself[(size_t)l * D * D + (size_t)k * D + n];
    } else {
        int r  = (k - D) >> 8;
        int kk = (k - D) & 255;
        v = Wrel[(((size_t)l * RNUM + r) * D + kk) * (size_t)D + n];
    }
    d_Wbig[i] = __float2half_rn(v);
}

// ---------------- CSR aggregation: warp per (dst node, half-row), fp32 accum ----------------
// 2 warps per node; each owns 128 of the 256 x-columns. Fewer regs, 2x warps in flight.
__global__ void __launch_bounds__(256) k_agg(const __half* __restrict__ Xr,
                                             __half* __restrict__ X, int n, int e) {
    int gw   = (blockIdx.x * blockDim.x + threadIdx.x) >> 5;
    int w    = gw >> 1;          // node
    int half = gw & 1;           // which 128-col half of x
    int lane = threadIdx.x & 31;
    if (w >= n) return;
    const int beg = d_Off[w];
    const int end = (w == n - 1) ? e : d_Off[w + 1];
    const int coloff = (half << 7) + (lane << 2);   // half*128 + lane*4 (halves)

    float acc[4][4];
#pragma unroll
    for (int t = 0; t < 4; t++)
#pragma unroll
        for (int q = 0; q < 4; q++) acc[t][q] = 0.0f;

    for (int j = beg; j < end; j++) {
        int pk = d_CsrE[j];
        int s  = pk >> 2;
        int t  = pk & 3;
        uint2 v = *reinterpret_cast<const uint2*>(Xr + (size_t)s * KDIM + coloff);
        const __half2* hp = reinterpret_cast<const __half2*>(&v);
        float2 f0 = __half22float2(hp[0]);
        float2 f1 = __half22float2(hp[1]);
        float* a = acc[t];
        a[0] += f0.x; a[1] += f0.y; a[2] += f1.x; a[3] += f1.y;
    }

    const float id = d_InvDeg[w];
#pragma unroll
    for (int t = 0; t < 4; t++) {
        __half2 h0 = __floats2half2_rn(acc[t][0] * id, acc[t][1] * id);
        __half2 h1 = __floats2half2_rn(acc[t][2] * id, acc[t][3] * id);
        uint2 st;
        st.x = *reinterpret_cast<uint32_t*>(&h0);
        st.y = *reinterpret_cast<uint32_t*>(&h1);
        *reinterpret_cast<uint2*>(X + (size_t)w * KDIM + D + (t << 8) + coloff) = st;
    }
}

// ---------------- fused fp16 mma.sync GEMM (4-stage cp.async, prefetch distance 3) ------------
#define BM 128
#define BN 256
#define KT 32                  // halves per k-tile
#define NKT (KDIM / KT)        // 40
#define ASTRB 80               // padded row stride bytes (32 halves + 8 pad)
#define ABYTES (BM * ASTRB)    // 10240
#define BBYTES (BN * ASTRB)    // 20480
#define STGB (ABYTES + BBYTES) // 30720
#define NSTAGE 4
#define GEMM_SMEM (NSTAGE * STGB)   // 122880

__global__ void __launch_bounds__(256, 1)
k_gemm(const __half* __restrict__ A, const __half* __restrict__ Wb,
       const float* __restrict__ bias, float* __restrict__ out_node,
       __half* __restrict__ xnext, int l, int M)
{
    extern __shared__ char smem[];
    const int tid    = threadIdx.x;
    const int lane   = tid & 31;
    const int wid    = tid >> 5;
    const int warp_m = wid & 1;
    const int warp_n = wid >> 1;
    const int brow   = blockIdx.x * BM;
    const uint32_t sbase = smem_u32(smem);

    float acc[4][8][4];
#pragma unroll
    for (int a = 0; a < 4; a++)
#pragma unroll
        for (int b = 0; b < 8; b++)
#pragma unroll
            for (int c = 0; c < 4; c++) acc[a][b][c] = 0.0f;

    auto issue = [&](int kt) {
        const int buf = kt & (NSTAGE - 1);
        const uint32_t abase = sbase + buf * STGB;
        const uint32_t bbase = abase + ABYTES;
        const int k0 = kt * KT;
#pragma unroll
        for (int i = 0; i < 2; i++) {           // A: 512 16B-chunks
            int j = tid + (i << 8);
            int row = j >> 2, c = j & 3;
            int gr = brow + row;
            const __half* sp = A + (size_t)(gr < M ? gr : 0) * KDIM + k0 + (c << 3);
            uint32_t dp = abase + row * ASTRB + (c << 4);
            uint32_t sz = (gr < M) ? 16u : 0u;
            asm volatile("cp.async.cg.shared.global [%0], [%1], 16, %2;"
                         :: "r"(dp), "l"(sp), "r"(sz));
        }
#pragma unroll
        for (int i = 0; i < 4; i++) {           // B: 1024 16B-chunks
            int j = tid + (i << 8);
            int row = j >> 2, c = j & 3;
            const __half* sp = Wb + (size_t)row * KDIM + k0 + (c << 3);
            uint32_t dp = bbase + row * ASTRB + (c << 4);
            asm volatile("cp.async.cg.shared.global [%0], [%1], 16;"
                         :: "r"(dp), "l"(sp));
        }
        asm volatile("cp.async.commit_group;");
    };

    issue(0);
    issue(1);
    issue(2);

#pragma unroll 1
    for (int kt = 0; kt < NKT; kt++) {
        if (kt < NKT - 2)       asm volatile("cp.async.wait_group 2;");
        else if (kt == NKT - 2) asm volatile("cp.async.wait_group 1;");
        else                    asm volatile("cp.async.wait_group 0;");
        __syncthreads();
        if (kt + 3 < NKT) issue(kt + 3);

        const int buf = kt & (NSTAGE - 1);
        const uint32_t abase = sbase + buf * STGB + (warp_m * 64) * ASTRB;
        const uint32_t bbase = sbase + buf * STGB + ABYTES + (warp_n * 64) * ASTRB;

        uint32_t breg[8][4];
#pragma unroll
        for (int n8 = 0; n8 < 8; n8++) {
            uint32_t addr = bbase + ((n8 << 3) + (lane & 7)) * ASTRB + ((lane >> 3) << 4);
            ldmx4(breg[n8], addr);
        }
#pragma unroll
        for (int kh = 0; kh < 2; kh++) {
            uint32_t areg[4][4];
#pragma unroll
            for (int mt = 0; mt < 4; mt++) {
                uint32_t addr = abase + ((mt << 4) + (lane & 15)) * ASTRB
                              + (kh << 5) + ((lane >> 4) << 4);
                ldmx4(areg[mt], addr);
            }
#pragma unroll
            for (int mt = 0; mt < 4; mt++)
#pragma unroll
                for (int n8 = 0; n8 < 8; n8++)
                    mma16(acc[mt][n8], areg[mt], breg[n8][(kh << 1)], breg[n8][(kh << 1) + 1]);
        }
    }

    // ---- epilogue: bias + relu -> out fp32; xnext fp16 ----
#pragma unroll
    for (int mt = 0; mt < 4; mt++) {
        int r0 = brow + warp_m * 64 + (mt << 4) + (lane >> 2);
#pragma unroll
        for (int hf = 0; hf < 2; hf++) {
            int r = r0 + (hf << 3);
            if (r < M) {
#pragma unroll
                for (int n8 = 0; n8 < 8; n8++) {
                    int c = warp_n * 64 + (n8 << 3) + ((lane & 3) << 1);
                    float v0 = fmaxf(acc[mt][n8][(hf << 1) + 0] + bias[c], 0.0f);
                    float v1 = fmaxf(acc[mt][n8][(hf << 1) + 1] + bias[c + 1], 0.0f);
                    *reinterpret_cast<float2*>(out_node + (size_t)r * NCTX + l * D + c) =
                        make_float2(v0, v1);
                    if (xnext) {
                        __half2 hv = __floats2half2_rn(v0, v1);
                        *reinterpret_cast<uint32_t*>(xnext + (size_t)r * KDIM + c) =
                            *reinterpret_cast<uint32_t*>(&hv);
                    }
                }
            }
        }
    }
}

// ---------------- fused pooling + broadcast: one block per graph (batch sorted) --------------
__global__ void __launch_bounds__(256)
k_pool(const int* __restrict__ batch, const int* __restrict__ reaction,
       float* __restrict__ out_node, float* __restrict__ gout, int n) {
    __shared__ float gctx[GCTX];
    const int gg  = blockIdx.x;
    const int tid = threadIdx.x;
    int lo = 0, hi = n;
    while (lo < hi) { int m = (lo + hi) >> 1; if (batch[m] < gg) lo = m + 1; else hi = m; }
    const int s = lo;
    hi = n;
    while (lo < hi) { int m = (lo + hi) >> 1; if (batch[m] <= gg) lo = m + 1; else hi = m; }
    const int e2 = lo;
    const float inv = 1.0f / fmaxf((float)(e2 - s), 1.0f);
    float a0 = 0.f, a1 = 0.f, a2 = 0.f;
    for (int node = s; node < e2; node++) {
        const float* row = out_node + (size_t)node * NCTX;
        a0 += row[tid];
        a1 += row[tid + 256];
        a2 += row[tid + 512];
    }
    gctx[tid]       = a0 * inv;
    gctx[tid + 256] = a1 * inv;
    gctx[tid + 512] = a2 * inv;
    if (tid < NRXN) gctx[ENCD + tid] = (tid == reaction[gg]) ? 1.0f : 0.0f;
    __syncthreads();
    float* gp = gout + (size_t)gg * GCTX;
    for (int c = tid; c < GCTX; c += 256) gp[c] = gctx[c];
    for (int node = s; node < e2; node++) {
        float* op = out_node + (size_t)node * NCTX + ENCD + D;
        for (int c = tid; c < GCTX; c += 256) op[c] = gctx[c];
    }
}

// ---------------- host launcher ----------------
extern "C" void kernel_launch(void* const* d_in, const int* in_sizes, int n_in,
                              void* d_out, int out_size) {
    const float* node_feature = (const float*)d_in[0];
    const float* flag_W       = (const float*)d_in[1];
    const float* flag_b       = (const float*)d_in[2];
    const float* W_self       = (const float*)d_in[3];
    const float* b_self       = (const float*)d_in[4];
    const float* W_rel        = (const float*)d_in[5];
    const int*   edge_src     = (const int*)d_in[6];
    const int*   edge_dst     = (const int*)d_in[7];
    const int*   edge_type    = (const int*)d_in[8];
    const int*   batch        = (const int*)d_in[9];
    const int*   reaction     = (const int*)d_in[10];
    const int*   center_mask  = (const int*)d_in[11];

    const int n = in_sizes[9];
    const int e = in_sizes[6];
    const int g = in_sizes[10];

    float* out  = (float*)d_out;
    float* gout = out + (size_t)n * NCTX;

    const int TPB = 256;
    auto blocks = [](long long total, int tpb) { return (unsigned)((total + tpb - 1) / tpb); };

    cudaFuncSetAttribute(k_gemm, cudaFuncAttributeMaxDynamicSharedMemorySize, GEMM_SMEM);

    __half *xa, *xb, *wb;
    int* degi;
    cudaGetSymbolAddress((void**)&xa,   d_XA);
    cudaGetSymbolAddress((void**)&xb,   d_XB);
    cudaGetSymbolAddress((void**)&wb,   d_Wbig);
    cudaGetSymbolAddress((void**)&degi, d_DegI);

    // ---- CSR build (once) + weights (all layers, once) ----
    k_zero_i<<<blocks(n, TPB), TPB>>>(degi, n);
    k_deg<<<blocks(e, TPB), TPB>>>(edge_dst, e);
    k_scan<<<1, 1024>>>(n);
    k_scatter<<<blocks(e, TPB), TPB>>>(edge_src, edge_dst, edge_type, e);
    k_invdeg<<<blocks(n, TPB), TPB>>>(n);
    k_wcat<<<blocks((long long)LNUM * D * KDIM, TPB), TPB>>>(W_self, W_rel);

    // ---- init ----
    k_init<<<blocks((long long)n * 64, TPB), TPB>>>(node_feature, flag_W, flag_b,
                                                    center_mask, xa, out, n);

    __half* cur = xa;
    __half* nxt = xb;
    const unsigned gemm_grid = blocks(n, BM);
    for (int l = 0; l < LNUM; l++) {
        k_agg<<<blocks((long long)n * 64, TPB), TPB>>>(cur, cur, n, e);
        k_gemm<<<gemm_grid, 256, GEMM_SMEM>>>(cur, wb + (size_t)l * D * KDIM,
                                              b_self + (size_t)l * D, out,
                                              (l < LNUM - 1) ? nxt : nullptr, l, n);
        if (l < LNUM - 1) { __half* t = cur; cur = nxt; nxt = t; }
    }

    k_pool<<<g, 256>>>(batch, reaction, out, gout, n);
}

// round 14
// speedup vs baseline: 1.2253x; 1.0800x over previous
#include <cuda_runtime.h>
#include <cuda_fp16.h>
#include <cstdint>

#define D 256
#define LNUM 3
#define RNUM 4
#define NRXN 10
#define NMAX 100000
#define EMAX 400000
#define GMAX 2000
#define KDIM 1280    // halves: [x(256) | S0..S3 (4*256)]
#define ENCD 768
#define GCTX 778
#define NCTX 1802

// ---------------- scratch ----------------
__device__ __half d_XA[(size_t)NMAX * KDIM];
__device__ __half d_XB[(size_t)NMAX * KDIM];
__device__ __half d_Wbig[LNUM * D * KDIM];   // [l][n][k], fp16
__device__ int    d_DegI[NMAX];
__device__ float  d_InvDeg[NMAX];
__device__ int    d_Off[NMAX];
__device__ int    d_Cursor[NMAX];
__device__ int    d_CsrE[EMAX];              // packed src*4 + type, grouped by dst

// ---------------- helpers ----------------
__device__ __forceinline__ uint32_t smem_u32(const void* p) {
    uint32_t a;
    asm("{ .reg .u64 t; cvta.to.shared.u64 t, %1; cvt.u32.u64 %0, t; }" : "=r"(a) : "l"(p));
    return a;
}
__device__ __forceinline__ void mma16(float* c, const uint32_t* a, uint32_t b0, uint32_t b1) {
    asm volatile("mma.sync.aligned.m16n8k16.row.col.f32.f16.f16.f32 "
        "{%0,%1,%2,%3}, {%4,%5,%6,%7}, {%8,%9}, {%0,%1,%2,%3};"
        : "+f"(c[0]), "+f"(c[1]), "+f"(c[2]), "+f"(c[3])
        : "r"(a[0]), "r"(a[1]), "r"(a[2]), "r"(a[3]), "r"(b0), "r"(b1));
}
__device__ __forceinline__ void ldmx4(uint32_t* r, uint32_t addr) {
    asm volatile("ldmatrix.sync.aligned.m8n8.x4.shared.b16 {%0,%1,%2,%3}, [%4];"
        : "=r"(r[0]), "=r"(r[1]), "=r"(r[2]), "=r"(r[3]) : "r"(addr));
}

// ---------------- small kernels ----------------
__global__ void k_zero_i(int* p, int n) {
    int i = blockIdx.x * blockDim.x + threadIdx.x;
    if (i < n) p[i] = 0;
}

// x0 = nf + flag_b + mask*flag_W[1] (fp16 RNE -> X cols 0..255); nf copy -> out [768:1024)
__global__ void k_init(const float* __restrict__ nf, const float* __restrict__ flagW,
                       const float* __restrict__ flagb, const int* __restrict__ mask,
                       __half* __restrict__ X, float* __restrict__ out_node, int n) {
    long long i = (long long)blockIdx.x * blockDim.x + threadIdx.x;
    if (i >= (long long)n * 64) return;
    int node = (int)(i >> 6);
    int c4   = (int)(i & 63);
    float4 v = reinterpret_cast<const float4*>(nf)[i];
    float4 b = reinterpret_cast<const float4*>(flagb)[c4];
    float  m = (mask[node] != 0) ? 1.0f : 0.0f;
    float4 w = reinterpret_cast<const float4*>(flagW + D)[c4];
    __half2 h0 = __floats2half2_rn(v.x + b.x + m * w.x, v.y + b.y + m * w.y);
    __half2 h1 = __floats2half2_rn(v.z + b.z + m * w.z, v.w + b.w + m * w.w);
    uint2 st;
    st.x = *reinterpret_cast<uint32_t*>(&h0);
    st.y = *reinterpret_cast<uint32_t*>(&h1);
    *reinterpret_cast<uint2*>(X + (size_t)node * KDIM + (c4 << 2)) = st;
    float* op = out_node + (size_t)node * NCTX + ENCD + (c4 << 2);
    reinterpret_cast<float2*>(op)[0] = make_float2(v.x, v.y);
    reinterpret_cast<float2*>(op)[1] = make_float2(v.z, v.w);
}

__global__ void k_deg(const int* __restrict__ dst, int e) {
    int i = blockIdx.x * blockDim.x + threadIdx.x;
    if (i < e) atomicAdd(&d_DegI[dst[i]], 1);
}
__global__ void k_invdeg(int n) {
    int i = blockIdx.x * blockDim.x + threadIdx.x;
    if (i < n) d_InvDeg[i] = 1.0f / fmaxf((float)d_DegI[i], 1.0f);
}

// single-block chunked exclusive scan of DegI -> Off, Cursor
__global__ void __launch_bounds__(1024) k_scan(int n) {
    __shared__ int ps[1024];
    const int t = threadIdx.x;
    const int chunk = (n + 1023) >> 10;
    const int s  = t * chunk;
    const int e2 = min(s + chunk, n);
    int sum = 0;
    for (int i = s; i < e2; i++) sum += d_DegI[i];
    ps[t] = sum;
    __syncthreads();
    for (int off = 1; off < 1024; off <<= 1) {
        int v = (t >= off) ? ps[t - off] : 0;
        __syncthreads();
        if (t >= off) ps[t] += v;
        __syncthreads();
    }
    int base = (t == 0) ? 0 : ps[t - 1];
    for (int i = s; i < e2; i++) {
        d_Off[i] = base;
        d_Cursor[i] = base;
        base += d_DegI[i];
    }
}

__global__ void k_scatter(const int* __restrict__ src, const int* __restrict__ dst,
                          const int* __restrict__ typ, int e) {
    int i = blockIdx.x * blockDim.x + threadIdx.x;
    if (i >= e) return;
    int pos = atomicAdd(&d_Cursor[dst[i]], 1);
    d_CsrE[pos] = (src[i] << 2) | typ[i];
}

// Wbig[l][n][k] fp16: k<256 -> W_self[l][k][n]; else r=(k-256)>>8, kk=(k-256)&255 -> W_rel[l][r][kk][n]
__global__ void k_wcat(const float* __restrict__ Wself, const float* __restrict__ Wrel) {
    int i = blockIdx.x * blockDim.x + threadIdx.x;
    if (i >= LNUM * D * KDIM) return;
    int l   = i / (D * KDIM);
    int rem = i % (D * KDIM);
    int n = rem / KDIM, k = rem % KDIM;
    float v;
    if (k < D) {
        v = Wself[(size_t)l * D * D + (size_t)k * D + n];
    } else {
        int r  = (k - D) >> 8;
        int kk = (k - D) & 255;
        v = Wrel[(((size_t)l * RNUM + r) * D + kk) * (size_t)D + n];
    }
    d_Wbig[i] = __float2half_rn(v);
}

// ---------------- CSR aggregation: warp per (dst node, half-row), fp32 accum ----------------
__global__ void __launch_bounds__(256) k_agg(const __half* __restrict__ Xr,
                                             __half* __restrict__ X, int n, int e) {
    int gw   = (blockIdx.x * blockDim.x + threadIdx.x) >> 5;
    int w    = gw >> 1;          // node
    int half = gw & 1;           // which 128-col half of x
    int lane = threadIdx.x & 31;
    if (w >= n) return;
    const int beg = d_Off[w];
    const int end = (w == n - 1) ? e : d_Off[w + 1];
    const int coloff = (half << 7) + (lane << 2);   // half*128 + lane*4 (halves)

    float acc[4][4];
#pragma unroll
    for (int t = 0; t < 4; t++)
#pragma unroll
        for (int q = 0; q < 4; q++) acc[t][q] = 0.0f;

    for (int j = beg; j < end; j++) {
        int pk = d_CsrE[j];
        int s  = pk >> 2;
        int t  = pk & 3;
        uint2 v = *reinterpret_cast<const uint2*>(Xr + (size_t)s * KDIM + coloff);
        const __half2* hp = reinterpret_cast<const __half2*>(&v);
        float2 f0 = __half22float2(hp[0]);
        float2 f1 = __half22float2(hp[1]);
        float* a = acc[t];
        a[0] += f0.x; a[1] += f0.y; a[2] += f1.x; a[3] += f1.y;
    }

    const float id = d_InvDeg[w];
#pragma unroll
    for (int t = 0; t < 4; t++) {
        __half2 h0 = __floats2half2_rn(acc[t][0] * id, acc[t][1] * id);
        __half2 h1 = __floats2half2_rn(acc[t][2] * id, acc[t][3] * id);
        uint2 st;
        st.x = *reinterpret_cast<uint32_t*>(&h0);
        st.y = *reinterpret_cast<uint32_t*>(&h1);
        *reinterpret_cast<uint2*>(X + (size_t)w * KDIM + D + (t << 8) + coloff) = st;
    }
}

// ---------------- fused fp16 mma.sync GEMM: BM=64, 2 CTAs/SM, 3-stage cp.async ------------
#define BM 64
#define BN 256
#define KT 32                  // halves per k-tile
#define NKT (KDIM / KT)        // 40
#define ASTRB 80               // padded row stride bytes (32 halves + 8 pad)
#define ABYTES (BM * ASTRB)    // 5120
#define BBYTES (BN * ASTRB)    // 20480
#define STGB (ABYTES + BBYTES) // 25600
#define NSTAGE 3
#define GEMM_SMEM (NSTAGE * STGB)   // 76800

__global__ void __launch_bounds__(256, 2)
k_gemm(const __half* __restrict__ A, const __half* __restrict__ Wb,
       const float* __restrict__ bias, float* __restrict__ out_node,
       __half* __restrict__ xnext, int l, int M)
{
    extern __shared__ char smem[];
    const int tid    = threadIdx.x;
    const int lane   = tid & 31;
    const int wid    = tid >> 5;
    const int warp_m = wid & 1;    // 2 x 32 rows
    const int warp_n = wid >> 1;   // 4 x 64 cols
    const int brow   = blockIdx.x * BM;
    const uint32_t sbase = smem_u32(smem);

    float acc[2][8][4];
#pragma unroll
    for (int a = 0; a < 2; a++)
#pragma unroll
        for (int b = 0; b < 8; b++)
#pragma unroll
            for (int c = 0; c < 4; c++) acc[a][b][c] = 0.0f;

    auto issue = [&](int kt) {
        const int buf = kt % 3;
        const uint32_t abase = sbase + buf * STGB;
        const uint32_t bbase = abase + ABYTES;
        const int k0 = kt * KT;
        {                                       // A: 256 16B-chunks (1 per thread)
            int row = tid >> 2, c = tid & 3;
            int gr = brow + row;
            const __half* sp = A + (size_t)(gr < M ? gr : 0) * KDIM + k0 + (c << 3);
            uint32_t dp = abase + row * ASTRB + (c << 4);
            uint32_t sz = (gr < M) ? 16u : 0u;
            asm volatile("cp.async.cg.shared.global [%0], [%1], 16, %2;"
                         :: "r"(dp), "l"(sp), "r"(sz));
        }
#pragma unroll
        for (int i = 0; i < 4; i++) {           // B: 1024 16B-chunks
            int j = tid + (i << 8);
            int row = j >> 2, c = j & 3;
            const __half* sp = Wb + (size_t)row * KDIM + k0 + (c << 3);
            uint32_t dp = bbase + row * ASTRB + (c << 4);
            asm volatile("cp.async.cg.shared.global [%0], [%1], 16;"
                         :: "r"(dp), "l"(sp));
        }
        asm volatile("cp.async.commit_group;");
    };

    issue(0);
    issue(1);

#pragma unroll 1
    for (int kt = 0; kt < NKT; kt++) {
        if (kt < NKT - 1) asm volatile("cp.async.wait_group 1;");
        else              asm volatile("cp.async.wait_group 0;");
        __syncthreads();
        if (kt + 2 < NKT) issue(kt + 2);

        const int buf = kt % 3;
        const uint32_t abase = sbase + buf * STGB + (warp_m * 32) * ASTRB;
        const uint32_t bbase = sbase + buf * STGB + ABYTES + (warp_n * 64) * ASTRB;

        uint32_t breg[8][4];
#pragma unroll
        for (int n8 = 0; n8 < 8; n8++) {
            uint32_t addr = bbase + ((n8 << 3) + (lane & 7)) * ASTRB + ((lane >> 3) << 4);
            ldmx4(breg[n8], addr);
        }
#pragma unroll
        for (int kh = 0; kh < 2; kh++) {
            uint32_t areg[2][4];
#pragma unroll
            for (int mt = 0; mt < 2; mt++) {
                uint32_t addr = abase + ((mt << 4) + (lane & 15)) * ASTRB
                              + (kh << 5) + ((lane >> 4) << 4);
                ldmx4(areg[mt], addr);
            }
#pragma unroll
            for (int mt = 0; mt < 2; mt++)
#pragma unroll
                for (int n8 = 0; n8 < 8; n8++)
                    mma16(acc[mt][n8], areg[mt], breg[n8][(kh << 1)], breg[n8][(kh << 1) + 1]);
        }
    }

    // ---- epilogue: bias + relu -> out fp32; xnext fp16 ----
#pragma unroll
    for (int mt = 0; mt < 2; mt++) {
        int r0 = brow + warp_m * 32 + (mt << 4) + (lane >> 2);
#pragma unroll
        for (int hf = 0; hf < 2; hf++) {
            int r = r0 + (hf << 3);
            if (r < M) {
#pragma unroll
                for (int n8 = 0; n8 < 8; n8++) {
                    int c = warp_n * 64 + (n8 << 3) + ((lane & 3) << 1);
                    float v0 = fmaxf(acc[mt][n8][(hf << 1) + 0] + bias[c], 0.0f);
                    float v1 = fmaxf(acc[mt][n8][(hf << 1) + 1] + bias[c + 1], 0.0f);
                    *reinterpret_cast<float2*>(out_node + (size_t)r * NCTX + l * D + c) =
                        make_float2(v0, v1);
                    if (xnext) {
                        __half2 hv = __floats2half2_rn(v0, v1);
                        *reinterpret_cast<uint32_t*>(xnext + (size_t)r * KDIM + c) =
                            *reinterpret_cast<uint32_t*>(&hv);
                    }
                }
            }
        }
    }
}

// ---------------- fused pooling + broadcast: one block per graph (batch sorted) --------------
__global__ void __launch_bounds__(256)
k_pool(const int* __restrict__ batch, const int* __restrict__ reaction,
       float* __restrict__ out_node, float* __restrict__ gout, int n) {
    __shared__ float gctx[GCTX];
    const int gg  = blockIdx.x;
    const int tid = threadIdx.x;
    int lo = 0, hi = n;
    while (lo < hi) { int m = (lo + hi) >> 1; if (batch[m] < gg) lo = m + 1; else hi = m; }
    const int s = lo;
    hi = n;
    while (lo < hi) { int m = (lo + hi) >> 1; if (batch[m] <= gg) lo = m + 1; else hi = m; }
    const int e2 = lo;
    const float inv = 1.0f / fmaxf((float)(e2 - s), 1.0f);
    float a0 = 0.f, a1 = 0.f, a2 = 0.f;
    for (int node = s; node < e2; node++) {
        const float* row = out_node + (size_t)node * NCTX;
        a0 += row[tid];
        a1 += row[tid + 256];
        a2 += row[tid + 512];
    }
    gctx[tid]       = a0 * inv;
    gctx[tid + 256] = a1 * inv;
    gctx[tid + 512] = a2 * inv;
    if (tid < NRXN) gctx[ENCD + tid] = (tid == reaction[gg]) ? 1.0f : 0.0f;
    __syncthreads();
    float* gp = gout + (size_t)gg * GCTX;
    for (int c = tid; c < GCTX; c += 256) gp[c] = gctx[c];
    for (int node = s; node < e2; node++) {
        float* op = out_node + (size_t)node * NCTX + ENCD + D;
        for (int c = tid; c < GCTX; c += 256) op[c] = gctx[c];
    }
}

// ---------------- host launcher ----------------
extern "C" void kernel_launch(void* const* d_in, const int* in_sizes, int n_in,
                              void* d_out, int out_size) {
    const float* node_feature = (const float*)d_in[0];
    const float* flag_W       = (const float*)d_in[1];
    const float* flag_b       = (const float*)d_in[2];
    const float* W_self       = (const float*)d_in[3];
    const float* b_self       = (const float*)d_in[4];
    const float* W_rel        = (const float*)d_in[5];
    const int*   edge_src     = (const int*)d_in[6];
    const int*   edge_dst     = (const int*)d_in[7];
    const int*   edge_type    = (const int*)d_in[8];
    const int*   batch        = (const int*)d_in[9];
    const int*   reaction     = (const int*)d_in[10];
    const int*   center_mask  = (const int*)d_in[11];

    const int n = in_sizes[9];
    const int e = in_sizes[6];
    const int g = in_sizes[10];

    float* out  = (float*)d_out;
    float* gout = out + (size_t)n * NCTX;

    const int TPB = 256;
    auto blocks = [](long long total, int tpb) { return (unsigned)((total + tpb - 1) / tpb); };

    cudaFuncSetAttribute(k_gemm, cudaFuncAttributeMaxDynamicSharedMemorySize, GEMM_SMEM);

    __half *xa, *xb, *wb;
    int* degi;
    cudaGetSymbolAddress((void**)&xa,   d_XA);
    cudaGetSymbolAddress((void**)&xb,   d_XB);
    cudaGetSymbolAddress((void**)&wb,   d_Wbig);
    cudaGetSymbolAddress((void**)&degi, d_DegI);

    // ---- CSR build (once) + weights (all layers, once) ----
    k_zero_i<<<blocks(n, TPB), TPB>>>(degi, n);
    k_deg<<<blocks(e, TPB), TPB>>>(edge_dst, e);
    k_scan<<<1, 1024>>>(n);
    k_scatter<<<blocks(e, TPB), TPB>>>(edge_src, edge_dst, edge_type, e);
    k_invdeg<<<blocks(n, TPB), TPB>>>(n);
    k_wcat<<<blocks((long long)LNUM * D * KDIM, TPB), TPB>>>(W_self, W_rel);

    // ---- init ----
    k_init<<<blocks((long long)n * 64, TPB), TPB>>>(node_feature, flag_W, flag_b,
                                                    center_mask, xa, out, n);

    __half* cur = xa;
    __half* nxt = xb;
    const unsigned gemm_grid = blocks(n, BM);
    for (int l = 0; l < LNUM; l++) {
        k_agg<<<blocks((long long)n * 64, TPB), TPB>>>(cur, cur, n, e);
        k_gemm<<<gemm_grid, 256, GEMM_SMEM>>>(cur, wb + (size_t)l * D * KDIM,
                                              b_self + (size_t)l * D, out,
                                              (l < LNUM - 1) ? nxt : nullptr, l, n);
        if (l < LNUM - 1) { __half* t = cur; cur = nxt; nxt = t; }
    }

    k_pool<<<g, 256>>>(batch, reaction, out, gout, n);
}